// round 13
// baseline (speedup 1.0000x reference)
#include <cuda_runtime.h>
#include <cuda_fp16.h>
#include <cstdint>

#define Bdim 16
#define Ndim 2048
#define Ddim 1024
#define Pdim 2048

// ---------------- device scratch (static; allocation-free rule) ----------------
__device__ __align__(256) __half g_x[(size_t)Bdim * Ndim * Ddim];    // x fp16 [b][n][d]
__device__ __align__(256) __half g_p[(size_t)Pdim * Ddim];           // (proto-0.5) [p][d]
__device__ __align__(256) float  g_ZT[(size_t)Bdim * Ndim * Pdim];   // Z^T [b][n][p]
__device__ __align__(256) uint2  g_list[(size_t)Bdim * Ndim * Pdim]; // (p, w) survivors
__device__ __align__(256) int    g_cnt[(size_t)Bdim * Ndim];         // survivors per (b,n)
__device__ __align__(256) float  g_rs[(size_t)Bdim * Ndim];          // 0.5 * row-sum of x
__device__ __align__(256) float  g_inv[(size_t)Bdim * Ndim];         // 1/sum_exp (full)
__device__ __align__(256) unsigned g_maxi[(size_t)Bdim * Ndim];      // ordered-uint max(z)

// ---------------- baseline-PTX helpers (sm_80-class only) ----------------------
__device__ __forceinline__ uint32_t smem_u32_of(const void* p) {
    uint32_t a;
    asm("{ .reg .u64 t; cvta.to.shared.u64 t, %1; cvt.u32.u64 %0, t; }" : "=r"(a) : "l"(p));
    return a;
}
__device__ __forceinline__ void cpasync16(uint32_t s, const void* g) {
    asm volatile("cp.async.cg.shared.global [%0], [%1], 16;" :: "r"(s), "l"(g));
}
#define CP_COMMIT() asm volatile("cp.async.commit_group;")
#define CP_WAIT(n)  asm volatile("cp.async.wait_group %0;" :: "n"(n))

__device__ __forceinline__ void ldsm4(uint32_t* r, uint32_t addr) {
    asm volatile("ldmatrix.sync.aligned.m8n8.x4.shared.b16 {%0,%1,%2,%3}, [%4];"
                 : "=r"(r[0]), "=r"(r[1]), "=r"(r[2]), "=r"(r[3]) : "r"(addr));
}
__device__ __forceinline__ void mma16816(float* c, const uint32_t* a, const uint32_t* b) {
    asm volatile("mma.sync.aligned.m16n8k16.row.col.f32.f16.f16.f32 "
                 "{%0,%1,%2,%3}, {%4,%5,%6,%7}, {%8,%9}, {%0,%1,%2,%3};"
                 : "+f"(c[0]), "+f"(c[1]), "+f"(c[2]), "+f"(c[3])
                 : "r"(a[0]), "r"(a[1]), "r"(a[2]), "r"(a[3]), "r"(b[0]), "r"(b[1]));
}

// ordered-uint encoding of fp32: monotone bijection, exact max via atomicMax
__device__ __forceinline__ unsigned enc_f(float f) {
    unsigned u = __float_as_uint(f);
    return (u & 0x80000000u) ? ~u : (u | 0x80000000u);
}
__device__ __forceinline__ float dec_f(unsigned k) {
    return __uint_as_float((k & 0x80000000u) ? (k & 0x7FFFFFFFu) : ~k);
}

// ---------------- k1 tiling: CTA tile 256(n) x 128(p), 512 thr, 4x4 warps -------
static constexpr int KT = 64;                 // fp16 k per stage (128 data bytes/row)
static constexpr int ROWB = 144;              // padded smem row bytes (128 + 16)
static constexpr int A_TILE_B = 256 * ROWB;   // 36864 (A = x, 256 n-rows)
static constexpr int B_TILE_B = 128 * ROWB;   // 18432 (B = proto, 128 p-rows)
static constexpr int STAGE_B = A_TILE_B + B_TILE_B;  // 55296
static constexpr int NSTG = 3;                // circular pipeline depth
static constexpr int UPAD = 260;              // u-tile smem stride (floats), 16B-aligned
static constexpr int DYN_SMEM = NSTG * STAGE_B;   // 165888 >= u-tile 133120

static constexpr float THR = 1e-3f;           // survivor threshold on exp(z - max)

// load one stage (A 256x128B + B 128x128B), 6 cp.async per thread (512 thr)
__device__ __forceinline__ void load_stage(
    const __half* gA, const __half* gB,
    int k0, uint32_t sbase, int tid)
{
#pragma unroll
    for (int j = 0; j < 4; j++) {             // A: 2048 chunks
        const int idx = tid + j * 512;
        const int row = idx >> 3, q = idx & 7;
        cpasync16(sbase + row * ROWB + q * 16,
                  gA + (size_t)row * Ddim + k0 + q * 8);
    }
#pragma unroll
    for (int j = 0; j < 2; j++) {             // B: 1024 chunks
        const int c = tid + j * 512;
        const int row = c >> 3, q = c & 7;
        cpasync16(sbase + A_TILE_B + row * ROWB + q * 16,
                  gB + (size_t)row * Ddim + k0 + q * 8);
    }
}

// compute one k64 stage: 4 k16-steps x (4 m-frags x 4 n-frags)
__device__ __forceinline__ void compute_stage(
    uint32_t sbase, int wm, int wn, uint32_t aoff, uint32_t boff,
    float acc[4][4][4])
{
    const uint32_t sA = sbase;
    const uint32_t sB = sbase + A_TILE_B;
#pragma unroll
    for (int ks = 0; ks < 4; ks++) {
        const uint32_t kb = ks * 32;
        uint32_t bf[8];
#pragma unroll
        for (int f = 0; f < 2; f++) {
            uint32_t off = (wn * 32 + f * 16) * ROWB + kb + boff;
            ldsm4(bf + f * 4, sB + off);
        }
#pragma unroll
        for (int mf = 0; mf < 4; mf++) {
            uint32_t off = (wm * 64 + mf * 16) * ROWB + kb + aoff;
            uint32_t af[4];
            ldsm4(af, sA + off);
#pragma unroll
            for (int nf = 0; nf < 4; nf++)
                mma16816(acc[mf][nf], af, bf + nf * 2);
        }
    }
}

// ---------------------------------------------------------------------------
// init_max: reset per-(b,n) running max to encode(-FLT_MAX) = 0x00800000
// ---------------------------------------------------------------------------
__global__ __launch_bounds__(256) void init_max() {
    g_maxi[blockIdx.x * 256 + threadIdx.x] = 0x00800000u;
}

// ---------------------------------------------------------------------------
// quant_x: x -> fp16, plus 0.5*row-sum (exact fp32) for the centering correction
// ---------------------------------------------------------------------------
__global__ __launch_bounds__(256) void quant_x(const float* __restrict__ x) {
    const int w = blockIdx.x * 8 + (threadIdx.x >> 5);
    const int lane = threadIdx.x & 31;
    const float4* row = (const float4*)(x + (size_t)w * Ddim);
    float s = 0.f;
#pragma unroll
    for (int i = 0; i < 8; i++) {
        float4 v = row[lane + 32 * i];
        s += (v.x + v.y) + (v.z + v.w);
        __half2 h01 = __floats2half2_rn(v.x, v.y);
        __half2 h23 = __floats2half2_rn(v.z, v.w);
        __half2* o = (__half2*)(g_x + (size_t)w * Ddim + (lane + 32 * i) * 4);
        o[0] = h01; o[1] = h23;
    }
#pragma unroll
    for (int o = 16; o > 0; o >>= 1) s += __shfl_xor_sync(0xFFFFFFFFu, s, o);
    if (lane == 0) g_rs[w] = 0.5f * s;
}
// quant_p: (proto - 0.5) -> fp16 row-major (k1 B-operand and sparse k3 rows)
__global__ __launch_bounds__(256) void quant_p(const float* __restrict__ proto) {
    int idx = blockIdx.x * 256 + threadIdx.x;
    g_p[idx] = __float2half_rn(proto[idx] - 0.5f);
}

// ---------------------------------------------------------------------------
// K1: Z^T[b][n][p] = x.(proto-0.5)^T + 0.5*rowsum(x) + gumbel, plus per-(b,n)
// running max via ordered-uint atomicMax. CTA tile 256(n) x 128(p), 512 thr.
// ---------------------------------------------------------------------------
__global__ __launch_bounds__(512) void k1_logits(const float* __restrict__ u) {
    extern __shared__ char smem[];
    const uint32_t smem_b = smem_u32_of(smem);
    const int tid = threadIdx.x, lane = tid & 31, wid = tid >> 5;
    const int wm = wid & 3;    // n direction, 4 warps x 64
    const int wn = wid >> 2;   // p direction, 4 warps x 32
    const int bn = blockIdx.x, bp = blockIdx.y, b = blockIdx.z;

    const __half* gA = g_x + ((size_t)b * Ndim + bn * 256) * Ddim;
    const __half* gB = g_p + (size_t)(bp * 128) * Ddim;

    const uint32_t aoff = (uint32_t)((lane & 15) * ROWB + ((lane & 16) ? 16 : 0));
    const uint32_t boff = (uint32_t)(((lane & 7) + ((lane & 16) ? 8 : 0)) * ROWB
                                     + ((lane & 8) ? 16 : 0));
    float acc[4][4][4];
#pragma unroll
    for (int mf = 0; mf < 4; mf++)
#pragma unroll
        for (int nf = 0; nf < 4; nf++)
#pragma unroll
            for (int e = 0; e < 4; e++) acc[mf][nf][e] = 0.f;

    load_stage(gA, gB, 0, smem_b, tid);
    CP_COMMIT();
    load_stage(gA, gB, KT, smem_b + STAGE_B, tid);
    CP_COMMIT();

    const int T = Ddim / KT;   // 16
    int s_cur = 0, s_nxt = 2;
    for (int t = 0; t < T; t++) {
        if (t == T - 1) { CP_WAIT(0); } else { CP_WAIT(1); }
        __syncthreads();
        if (t + 2 < T) {
            load_stage(gA, gB, (t + 2) * KT, smem_b + s_nxt * STAGE_B, tid);
            CP_COMMIT();
        }
        compute_stage(smem_b + s_cur * STAGE_B, wm, wn, aoff, boff, acc);
        s_cur = (s_cur == 2) ? 0 : s_cur + 1;
        s_nxt = (s_nxt == 2) ? 0 : s_nxt + 1;
    }

    // stage u tile [p: 128][n: 256] into smem (stride UPAD floats)
    __syncthreads();
    float* u_s = (float*)smem;
    const float* ug = u + ((size_t)b * Pdim + (size_t)bp * 128) * Ndim + bn * 256;
#pragma unroll
    for (int j = 0; j < 16; j++) {
        int idx = tid + j * 512;            // 0..8191 float4s
        int row = idx >> 6, c4 = idx & 63;  // row = p (0..127), c4 over 256 n
        float4 v = *(const float4*)(ug + (size_t)row * Ndim + c4 * 4);
        *(float4*)(u_s + row * UPAD + c4 * 4) = v;
    }
    __syncthreads();

    const int gID = lane >> 2, tg = lane & 3;
#pragma unroll
    for (int mf = 0; mf < 4; mf++) {
#pragma unroll
        for (int r2 = 0; r2 < 2; r2++) {
            const int nl = wm * 64 + mf * 16 + gID + r2 * 8;   // 0..255
            const size_t rn = (size_t)b * Ndim + bn * 256 + nl;
            const float rsv = g_rs[rn];
            const size_t rowbase = rn * Pdim + bp * 128;
            float zmax = -3.4e38f;
#pragma unroll
            for (int nf = 0; nf < 4; nf++) {
                const int pl = wn * 32 + nf * 8 + tg * 2;      // 0..127
                float u0 = u_s[pl * UPAD + nl];
                float u1 = u_s[(pl + 1) * UPAD + nl];
                float2 z;
                z.x = acc[mf][nf][r2 * 2 + 0] + rsv - __logf(-__logf(u0));
                z.y = acc[mf][nf][r2 * 2 + 1] + rsv - __logf(-__logf(u1));
                *(float2*)&g_ZT[rowbase + pl] = z;
                zmax = fmaxf(zmax, fmaxf(z.x, z.y));
            }
            zmax = fmaxf(zmax, __shfl_xor_sync(0xFFFFFFFFu, zmax, 1));
            zmax = fmaxf(zmax, __shfl_xor_sync(0xFFFFFFFFu, zmax, 2));
            if (tg == 0) atomicMax(&g_maxi[rn], enc_f(zmax));
        }
    }
}

// ---------------------------------------------------------------------------
// K2: single-pass softmax using precomputed max; deterministic ballot
// compaction of survivors (w > THR); 1/sum over the FULL sum.
// ---------------------------------------------------------------------------
__global__ __launch_bounds__(256) void k2_softmax() {
    int wid = threadIdx.x >> 5, lane = threadIdx.x & 31;
    int n = blockIdx.x * 8 + wid, b = blockIdx.y;
    size_t rn = (size_t)b * Ndim + n;
    size_t rb = rn * Pdim;
    const float4* row = (const float4*)(g_ZT + rb);
    const float m = dec_f(g_maxi[rn]);   // exact max (ordered-uint bijection)

    float s = 0.f;
    uint32_t cnt = 0;
    uint2* lst = g_list + rb;
#pragma unroll 2
    for (int i = 0; i < 16; i++) {
        int i4 = lane + 32 * i;
        float4 v = row[i4];
        float w4[4];
        w4[0] = __expf(v.x - m); w4[1] = __expf(v.y - m);
        w4[2] = __expf(v.z - m); w4[3] = __expf(v.w - m);
        s += (w4[0] + w4[1]) + (w4[2] + w4[3]);
#pragma unroll
        for (int j = 0; j < 4; j++) {
            bool keep = (w4[j] > THR);
            unsigned msk = __ballot_sync(0xFFFFFFFFu, keep);
            if (keep) {
                int off = __popc(msk & ((1u << lane) - 1u));
                lst[cnt + off] = make_uint2((unsigned)(i4 * 4 + j),
                                            __float_as_uint(w4[j]));
            }
            cnt += (uint32_t)__popc(msk);
        }
    }
#pragma unroll
    for (int o = 16; o > 0; o >>= 1) s += __shfl_xor_sync(0xFFFFFFFFu, s, o);
    if (lane == 0) {
        g_inv[rn] = 1.0f / s;
        g_cnt[rn] = (int)cnt;
    }
}

// ---------------------------------------------------------------------------
// K3 sparse: warp-per-(b,n). out[b][n][d] = inv * sum_j w_j * protoC[p_j][d] + 0.5
// ---------------------------------------------------------------------------
__global__ __launch_bounds__(256) void k3_sparse(float* __restrict__ out) {
    int wid = threadIdx.x >> 5, lane = threadIdx.x & 31;
    int n = blockIdx.x * 8 + wid, b = blockIdx.y;
    size_t rn = (size_t)b * Ndim + n;
    const uint2* __restrict__ lst = g_list + rn * Pdim;
    const int L = g_cnt[rn];
    const float inv = g_inv[rn];

    float acc[32];
#pragma unroll
    for (int k = 0; k < 32; k++) acc[k] = 0.f;

#pragma unroll 4
    for (int j = 0; j < L; j++) {
        uint2 e = lst[j];                       // broadcast load
        float w = __uint_as_float(e.y);
        const uint4* __restrict__ prow = (const uint4*)(g_p + (size_t)e.x * Ddim);
        uint4 pk[4];
#pragma unroll
        for (int q = 0; q < 4; q++) pk[q] = prow[lane + 32 * q];   // batched loads
#pragma unroll
        for (int q = 0; q < 4; q++) {
            const __half2* h = (const __half2*)&pk[q];
#pragma unroll
            for (int t = 0; t < 4; t++) {
                float2 f = __half22float2(h[t]);
                acc[q * 8 + t * 2 + 0] = fmaf(w, f.x, acc[q * 8 + t * 2 + 0]);
                acc[q * 8 + t * 2 + 1] = fmaf(w, f.y, acc[q * 8 + t * 2 + 1]);
            }
        }
    }

    float* orow = out + rn * Ddim;
#pragma unroll
    for (int q = 0; q < 4; q++) {
        int d0 = (lane + 32 * q) * 8;
        float4 o0, o1;
        o0.x = acc[q * 8 + 0] * inv + 0.5f; o0.y = acc[q * 8 + 1] * inv + 0.5f;
        o0.z = acc[q * 8 + 2] * inv + 0.5f; o0.w = acc[q * 8 + 3] * inv + 0.5f;
        o1.x = acc[q * 8 + 4] * inv + 0.5f; o1.y = acc[q * 8 + 5] * inv + 0.5f;
        o1.z = acc[q * 8 + 6] * inv + 0.5f; o1.w = acc[q * 8 + 7] * inv + 0.5f;
        *(float4*)(orow + d0) = o0;
        *(float4*)(orow + d0 + 4) = o1;
    }
}

// ---------------------------------------------------------------------------
extern "C" void kernel_launch(void* const* d_in, const int* in_sizes, int n_in,
                              void* d_out, int out_size)
{
    (void)in_sizes; (void)n_in; (void)out_size;
    const float* x     = (const float*)d_in[0];  // [B, N, D]
    const float* u     = (const float*)d_in[1];  // [B, P, N]
    const float* proto = (const float*)d_in[2];  // [P, D]
    float* out = (float*)d_out;                  // [B, N, D]

    cudaFuncSetAttribute(k1_logits, cudaFuncAttributeMaxDynamicSharedMemorySize, DYN_SMEM);

    init_max<<<(Bdim * Ndim) / 256, 256>>>();
    quant_x<<<(Bdim * Ndim) / 8, 256>>>(x);
    quant_p<<<(Pdim * Ddim) / 256, 256>>>(proto);

    dim3 g1(Ndim / 256, Pdim / 128, Bdim);
    k1_logits<<<g1, 512, DYN_SMEM>>>(u);

    dim3 g2(Ndim / 8, Bdim);
    k2_softmax<<<g2, 256>>>();

    dim3 g3(Ndim / 8, Bdim);
    k3_sparse<<<g3, 256>>>(out);
}

// round 14
// speedup vs baseline: 1.1486x; 1.1486x over previous
#include <cuda_runtime.h>
#include <cuda_fp16.h>
#include <cstdint>

#define Bdim 16
#define Ndim 2048
#define Ddim 1024
#define Pdim 2048

// ---------------- device scratch (static; allocation-free rule) ----------------
__device__ __align__(256) __half g_x[(size_t)Bdim * Ndim * Ddim];    // x fp16 [b][n][d]
__device__ __align__(256) __half g_p[(size_t)Pdim * Ddim];           // (proto-0.5) [p][d]
__device__ __align__(256) float  g_ZT[(size_t)Bdim * Ndim * Pdim];   // Z^T [b][n][p]
__device__ __align__(256) uint2  g_list[(size_t)Bdim * Ndim * Pdim]; // (p, w) survivors
__device__ __align__(256) int    g_cnt[(size_t)Bdim * Ndim];         // survivors per (b,n)
__device__ __align__(256) float  g_rs[(size_t)Bdim * Ndim];          // 0.5 * row-sum of x
__device__ __align__(256) float  g_inv[(size_t)Bdim * Ndim];         // 1/sum_exp (full)
__device__ __align__(256) unsigned g_maxi[(size_t)Bdim * Ndim];      // ordered-uint max(z)

// ---------------- baseline-PTX helpers (sm_80-class only) ----------------------
__device__ __forceinline__ uint32_t smem_u32_of(const void* p) {
    uint32_t a;
    asm("{ .reg .u64 t; cvta.to.shared.u64 t, %1; cvt.u32.u64 %0, t; }" : "=r"(a) : "l"(p));
    return a;
}
__device__ __forceinline__ void cpasync16(uint32_t s, const void* g) {
    asm volatile("cp.async.cg.shared.global [%0], [%1], 16;" :: "r"(s), "l"(g));
}
#define CP_COMMIT() asm volatile("cp.async.commit_group;")
#define CP_WAIT(n)  asm volatile("cp.async.wait_group %0;" :: "n"(n))

__device__ __forceinline__ void ldsm4(uint32_t* r, uint32_t addr) {
    asm volatile("ldmatrix.sync.aligned.m8n8.x4.shared.b16 {%0,%1,%2,%3}, [%4];"
                 : "=r"(r[0]), "=r"(r[1]), "=r"(r[2]), "=r"(r[3]) : "r"(addr));
}
__device__ __forceinline__ void mma16816(float* c, const uint32_t* a, const uint32_t* b) {
    asm volatile("mma.sync.aligned.m16n8k16.row.col.f32.f16.f16.f32 "
                 "{%0,%1,%2,%3}, {%4,%5,%6,%7}, {%8,%9}, {%0,%1,%2,%3};"
                 : "+f"(c[0]), "+f"(c[1]), "+f"(c[2]), "+f"(c[3])
                 : "r"(a[0]), "r"(a[1]), "r"(a[2]), "r"(a[3]), "r"(b[0]), "r"(b[1]));
}

// ordered-uint encoding of fp32: monotone bijection, exact max via atomicMax
__device__ __forceinline__ unsigned enc_f(float f) {
    unsigned u = __float_as_uint(f);
    return (u & 0x80000000u) ? ~u : (u | 0x80000000u);
}
__device__ __forceinline__ float dec_f(unsigned k) {
    return __uint_as_float((k & 0x80000000u) ? (k & 0x7FFFFFFFu) : ~k);
}

// ---------------- tiling constants (R12 proven config) ----------------
static constexpr int KT = 64;                 // fp16 k per stage (128 data bytes/row)
static constexpr int ROWB = 144;              // padded smem row bytes (128 + 16)
static constexpr int TILE_B = 128 * ROWB;     // 18432 per operand tile
static constexpr int STAGE_B = 2 * TILE_B;    // A, B = 36864
static constexpr int NSTG = 3;                // circular pipeline depth
static constexpr int DYN_SMEM = NSTG * STAGE_B;   // 110592; x2 CTAs/SM

static constexpr float THR = 1e-3f;           // survivor threshold on exp(z - max)
static constexpr int UROWB = 528;             // u-tile smem row stride (132 floats)

// load one stage (2 tiles x 128 rows x 128B), 8 cp.async per thread (256 thr)
__device__ __forceinline__ void load_stage(
    const __half* gA, const __half* gB,
    size_t Ks, int k0, uint32_t sbase, int tid)
{
    const __half* G[2] = {gA, gB};
#pragma unroll
    for (int j = 0; j < 8; j++) {
        const int idx = tid + j * 256;        // 0..2047
        const int tile = idx >> 10;
        const int c = idx & 1023;
        const int row = c >> 3, q = c & 7;
        cpasync16(sbase + tile * TILE_B + row * ROWB + q * 16,
                  G[tile] + (size_t)row * Ks + k0 + q * 8);
    }
}

// compute one k64 stage: 4 k16-steps x (4 m-frags x 4 n-frags)
__device__ __forceinline__ void compute_stage(
    uint32_t sbase, int wm, int wn, uint32_t aoff, uint32_t boff,
    float acc[4][4][4])
{
    const uint32_t sA = sbase;
    const uint32_t sB = sbase + TILE_B;
#pragma unroll
    for (int ks = 0; ks < 4; ks++) {
        const uint32_t kb = ks * 32;
        uint32_t bf[8];
#pragma unroll
        for (int f = 0; f < 2; f++) {
            uint32_t off = (wn * 32 + f * 16) * ROWB + kb + boff;
            ldsm4(bf + f * 4, sB + off);
        }
#pragma unroll
        for (int mf = 0; mf < 4; mf++) {
            uint32_t off = (wm * 64 + mf * 16) * ROWB + kb + aoff;
            uint32_t af[4];
            ldsm4(af, sA + off);
#pragma unroll
            for (int nf = 0; nf < 4; nf++)
                mma16816(acc[mf][nf], af, bf + nf * 2);
        }
    }
}

// ---------------------------------------------------------------------------
// quant_x: x -> fp16 + 0.5*row-sum (fp32) + init per-row max cell
// ---------------------------------------------------------------------------
__global__ __launch_bounds__(256) void quant_x(const float* __restrict__ x) {
    const int w = blockIdx.x * 8 + (threadIdx.x >> 5);
    const int lane = threadIdx.x & 31;
    const float4* row = (const float4*)(x + (size_t)w * Ddim);
    float s = 0.f;
#pragma unroll
    for (int i = 0; i < 8; i++) {
        float4 v = row[lane + 32 * i];
        s += (v.x + v.y) + (v.z + v.w);
        __half2 h01 = __floats2half2_rn(v.x, v.y);
        __half2 h23 = __floats2half2_rn(v.z, v.w);
        __half2* o = (__half2*)(g_x + (size_t)w * Ddim + (lane + 32 * i) * 4);
        o[0] = h01; o[1] = h23;
    }
#pragma unroll
    for (int o = 16; o > 0; o >>= 1) s += __shfl_xor_sync(0xFFFFFFFFu, s, o);
    if (lane == 0) {
        g_rs[w] = 0.5f * s;
        g_maxi[w] = 0x00800000u;   // encode(-FLT_MAX)
    }
}
// quant_p: (proto - 0.5) -> fp16 row-major (k1 B-operand and sparse k3 rows)
__global__ __launch_bounds__(256) void quant_p(const float* __restrict__ proto) {
    int idx = blockIdx.x * 256 + threadIdx.x;
    g_p[idx] = __float2half_rn(proto[idx] - 0.5f);
}

// ---------------------------------------------------------------------------
// K1: Z^T[b][n][p] = x.(proto-0.5)^T + 0.5*rowsum(x) + gumbel, plus per-(b,n)
// running max via ordered-uint atomicMax. u tile prefetched via cp.async into
// the dead pipeline buffers (1,2) during the last two GEMM stages.
// ---------------------------------------------------------------------------
__global__ __launch_bounds__(256, 2) void k1_logits(const float* __restrict__ u) {
    extern __shared__ char smem[];
    const uint32_t smem_b = smem_u32_of(smem);
    const int tid = threadIdx.x, lane = tid & 31, wid = tid >> 5;
    const int wm = wid & 1, wn = wid >> 1;
    const int bn = blockIdx.x, bp = blockIdx.y, b = blockIdx.z;

    const __half* gA = g_x + ((size_t)b * Ndim + bn * 128) * Ddim;
    const __half* gB = g_p + (size_t)(bp * 128) * Ddim;
    const float* ug = u + ((size_t)b * Pdim + (size_t)bp * 128) * Ndim + bn * 128;

    const uint32_t aoff = (uint32_t)((lane & 15) * ROWB + ((lane & 16) ? 16 : 0));
    const uint32_t boff = (uint32_t)(((lane & 7) + ((lane & 16) ? 8 : 0)) * ROWB
                                     + ((lane & 8) ? 16 : 0));
    float acc[4][4][4];
#pragma unroll
    for (int mf = 0; mf < 4; mf++)
#pragma unroll
        for (int nf = 0; nf < 4; nf++)
#pragma unroll
            for (int e = 0; e < 4; e++) acc[mf][nf][e] = 0.f;

    load_stage(gA, gB, (size_t)Ddim, 0, smem_b, tid);
    CP_COMMIT();
    load_stage(gA, gB, (size_t)Ddim, KT, smem_b + STAGE_B, tid);
    CP_COMMIT();

    const int T = Ddim / KT;   // 16
    int s_cur = 0, s_nxt = 2;
    for (int t = 0; t < T; t++) {
        CP_WAIT(1);            // stage t complete; newest group may pend
        __syncthreads();
        if (t + 2 < T) {
            load_stage(gA, gB, (size_t)Ddim, (t + 2) * KT,
                       smem_b + s_nxt * STAGE_B, tid);
            CP_COMMIT();
        } else {
            // u-tile prefetch into dead buffers: rows [0,64) at t=T-2,
            // rows [64,128) at t=T-1. Region [STAGE_B, STAGE_B+67584)
            // spans buffers 1..2, each free when written (top-of-iter sync).
            const int rbase = (t + 2 == T) ? 0 : 64;
#pragma unroll
            for (int j = 0; j < 8; j++) {
                int idx = tid + j * 256;            // 0..2047
                int row = rbase + (idx >> 5), c4 = idx & 31;
                cpasync16(smem_b + STAGE_B + row * UROWB + c4 * 16,
                          ug + (size_t)row * Ndim + c4 * 4);
            }
            CP_COMMIT();
        }
        compute_stage(smem_b + s_cur * STAGE_B, wm, wn, aoff, boff, acc);
        s_cur = (s_cur == 2) ? 0 : s_cur + 1;
        s_nxt = (s_nxt == 2) ? 0 : s_nxt + 1;
    }

    CP_WAIT(0);                // u tile fully arrived
    __syncthreads();
    const float* u_s = (const float*)(smem + STAGE_B);

    const int gID = lane >> 2, tg = lane & 3;
#pragma unroll
    for (int mf = 0; mf < 4; mf++) {
#pragma unroll
        for (int r2 = 0; r2 < 2; r2++) {
            const int nl = wm * 64 + mf * 16 + gID + r2 * 8;
            const size_t rn = (size_t)b * Ndim + bn * 128 + nl;
            const float rsv = g_rs[rn];
            const size_t rowbase = rn * Pdim + bp * 128;
            float zmax = -3.4e38f;
#pragma unroll
            for (int nf = 0; nf < 4; nf++) {
                const int pl = wn * 32 + nf * 8 + tg * 2;
                float u0 = u_s[pl * 132 + nl];
                float u1 = u_s[(pl + 1) * 132 + nl];
                float2 z;
                z.x = acc[mf][nf][r2 * 2 + 0] + rsv - __logf(-__logf(u0));
                z.y = acc[mf][nf][r2 * 2 + 1] + rsv - __logf(-__logf(u1));
                *(float2*)&g_ZT[rowbase + pl] = z;
                zmax = fmaxf(zmax, fmaxf(z.x, z.y));
            }
            zmax = fmaxf(zmax, __shfl_xor_sync(0xFFFFFFFFu, zmax, 1));
            zmax = fmaxf(zmax, __shfl_xor_sync(0xFFFFFFFFu, zmax, 2));
            if (tg == 0) atomicMax(&g_maxi[rn], enc_f(zmax));
        }
    }
}

// ---------------------------------------------------------------------------
// K2: single-pass softmax using precomputed max; deterministic ballot
// compaction of survivors (w > THR); 1/sum over the FULL sum.
// ---------------------------------------------------------------------------
__global__ __launch_bounds__(256) void k2_softmax() {
    int wid = threadIdx.x >> 5, lane = threadIdx.x & 31;
    int n = blockIdx.x * 8 + wid, b = blockIdx.y;
    size_t rn = (size_t)b * Ndim + n;
    size_t rb = rn * Pdim;
    const float4* row = (const float4*)(g_ZT + rb);
    const float m = dec_f(g_maxi[rn]);   // exact max (ordered-uint bijection)

    float s = 0.f;
    uint32_t cnt = 0;
    uint2* lst = g_list + rb;
#pragma unroll 2
    for (int i = 0; i < 16; i++) {
        int i4 = lane + 32 * i;
        float4 v = row[i4];
        float w4[4];
        w4[0] = __expf(v.x - m); w4[1] = __expf(v.y - m);
        w4[2] = __expf(v.z - m); w4[3] = __expf(v.w - m);
        s += (w4[0] + w4[1]) + (w4[2] + w4[3]);
#pragma unroll
        for (int j = 0; j < 4; j++) {
            bool keep = (w4[j] > THR);
            unsigned msk = __ballot_sync(0xFFFFFFFFu, keep);
            if (keep) {
                int off = __popc(msk & ((1u << lane) - 1u));
                lst[cnt + off] = make_uint2((unsigned)(i4 * 4 + j),
                                            __float_as_uint(w4[j]));
            }
            cnt += (uint32_t)__popc(msk);
        }
    }
#pragma unroll
    for (int o = 16; o > 0; o >>= 1) s += __shfl_xor_sync(0xFFFFFFFFu, s, o);
    if (lane == 0) {
        g_inv[rn] = 1.0f / s;
        g_cnt[rn] = (int)cnt;
    }
}

// ---------------------------------------------------------------------------
// K3 sparse: warp-per-(b,n). out[b][n][d] = inv * sum_j w_j * protoC[p_j][d] + 0.5
// ---------------------------------------------------------------------------
__global__ __launch_bounds__(256) void k3_sparse(float* __restrict__ out) {
    int wid = threadIdx.x >> 5, lane = threadIdx.x & 31;
    int n = blockIdx.x * 8 + wid, b = blockIdx.y;
    size_t rn = (size_t)b * Ndim + n;
    const uint2* __restrict__ lst = g_list + rn * Pdim;
    const int L = g_cnt[rn];
    const float inv = g_inv[rn];

    float acc[32];
#pragma unroll
    for (int k = 0; k < 32; k++) acc[k] = 0.f;

#pragma unroll 4
    for (int j = 0; j < L; j++) {
        uint2 e = lst[j];                       // broadcast load
        float w = __uint_as_float(e.y);
        const uint4* __restrict__ prow = (const uint4*)(g_p + (size_t)e.x * Ddim);
        uint4 pk[4];
#pragma unroll
        for (int q = 0; q < 4; q++) pk[q] = prow[lane + 32 * q];   // batched loads
#pragma unroll
        for (int q = 0; q < 4; q++) {
            const __half2* h = (const __half2*)&pk[q];
#pragma unroll
            for (int t = 0; t < 4; t++) {
                float2 f = __half22float2(h[t]);
                acc[q * 8 + t * 2 + 0] = fmaf(w, f.x, acc[q * 8 + t * 2 + 0]);
                acc[q * 8 + t * 2 + 1] = fmaf(w, f.y, acc[q * 8 + t * 2 + 1]);
            }
        }
    }

    float* orow = out + rn * Ddim;
#pragma unroll
    for (int q = 0; q < 4; q++) {
        int d0 = (lane + 32 * q) * 8;
        float4 o0, o1;
        o0.x = acc[q * 8 + 0] * inv + 0.5f; o0.y = acc[q * 8 + 1] * inv + 0.5f;
        o0.z = acc[q * 8 + 2] * inv + 0.5f; o0.w = acc[q * 8 + 3] * inv + 0.5f;
        o1.x = acc[q * 8 + 4] * inv + 0.5f; o1.y = acc[q * 8 + 5] * inv + 0.5f;
        o1.z = acc[q * 8 + 6] * inv + 0.5f; o1.w = acc[q * 8 + 7] * inv + 0.5f;
        *(float4*)(orow + d0) = o0;
        *(float4*)(orow + d0 + 4) = o1;
    }
}

// ---------------------------------------------------------------------------
extern "C" void kernel_launch(void* const* d_in, const int* in_sizes, int n_in,
                              void* d_out, int out_size)
{
    (void)in_sizes; (void)n_in; (void)out_size;
    const float* x     = (const float*)d_in[0];  // [B, N, D]
    const float* u     = (const float*)d_in[1];  // [B, P, N]
    const float* proto = (const float*)d_in[2];  // [P, D]
    float* out = (float*)d_out;                  // [B, N, D]

    cudaFuncSetAttribute(k1_logits, cudaFuncAttributeMaxDynamicSharedMemorySize, DYN_SMEM);

    quant_x<<<(Bdim * Ndim) / 8, 256>>>(x);
    quant_p<<<(Pdim * Ddim) / 256, 256>>>(proto);

    dim3 g1(Ndim / 128, Pdim / 128, Bdim);
    k1_logits<<<g1, 256, DYN_SMEM>>>(u);

    dim3 g2(Ndim / 8, Bdim);
    k2_softmax<<<g2, 256>>>();

    dim3 g3(Ndim / 8, Bdim);
    k3_sparse<<<g3, 256>>>(out);
}

// round 15
// speedup vs baseline: 1.1565x; 1.0069x over previous
#include <cuda_runtime.h>
#include <cuda_fp16.h>
#include <cstdint>

#define Bdim 16
#define Ndim 2048
#define Ddim 1024
#define Pdim 2048

// ---------------- device scratch (static; allocation-free rule) ----------------
__device__ __align__(256) __half g_x[(size_t)Bdim * Ndim * Ddim];    // x fp16 [b][n][d]
__device__ __align__(256) __half g_p[(size_t)Pdim * Ddim];           // (proto-0.5) [p][d]
__device__ __align__(256) float  g_ZT[(size_t)Bdim * Ndim * Pdim];   // Z^T [b][n][p]
__device__ __align__(256) float  g_rs[(size_t)Bdim * Ndim];          // 0.5 * row-sum of x
__device__ __align__(256) unsigned g_maxi[(size_t)Bdim * Ndim];      // ordered-uint max(z)

// ---------------- baseline-PTX helpers (sm_80-class only) ----------------------
__device__ __forceinline__ uint32_t smem_u32_of(const void* p) {
    uint32_t a;
    asm("{ .reg .u64 t; cvta.to.shared.u64 t, %1; cvt.u32.u64 %0, t; }" : "=r"(a) : "l"(p));
    return a;
}
__device__ __forceinline__ void cpasync16(uint32_t s, const void* g) {
    asm volatile("cp.async.cg.shared.global [%0], [%1], 16;" :: "r"(s), "l"(g));
}
#define CP_COMMIT() asm volatile("cp.async.commit_group;")
#define CP_WAIT(n)  asm volatile("cp.async.wait_group %0;" :: "n"(n))

__device__ __forceinline__ void ldsm4(uint32_t* r, uint32_t addr) {
    asm volatile("ldmatrix.sync.aligned.m8n8.x4.shared.b16 {%0,%1,%2,%3}, [%4];"
                 : "=r"(r[0]), "=r"(r[1]), "=r"(r[2]), "=r"(r[3]) : "r"(addr));
}
__device__ __forceinline__ void mma16816(float* c, const uint32_t* a, const uint32_t* b) {
    asm volatile("mma.sync.aligned.m16n8k16.row.col.f32.f16.f16.f32 "
                 "{%0,%1,%2,%3}, {%4,%5,%6,%7}, {%8,%9}, {%0,%1,%2,%3};"
                 : "+f"(c[0]), "+f"(c[1]), "+f"(c[2]), "+f"(c[3])
                 : "r"(a[0]), "r"(a[1]), "r"(a[2]), "r"(a[3]), "r"(b[0]), "r"(b[1]));
}

// ordered-uint encoding of fp32: monotone bijection, exact max via atomicMax
__device__ __forceinline__ unsigned enc_f(float f) {
    unsigned u = __float_as_uint(f);
    return (u & 0x80000000u) ? ~u : (u | 0x80000000u);
}
__device__ __forceinline__ float dec_f(unsigned k) {
    return __uint_as_float((k & 0x80000000u) ? (k & 0x7FFFFFFFu) : ~k);
}

// ---------------- tiling constants (R12/R14 proven config) ----------------
static constexpr int KT = 64;                 // fp16 k per stage (128 data bytes/row)
static constexpr int ROWB = 144;              // padded smem row bytes (128 + 16)
static constexpr int TILE_B = 128 * ROWB;     // 18432 per operand tile
static constexpr int STAGE_B = 2 * TILE_B;    // A, B = 36864
static constexpr int NSTG = 3;                // circular pipeline depth
static constexpr int DYN_SMEM = NSTG * STAGE_B;   // 110592; x2 CTAs/SM

static constexpr float THR = 1e-3f;           // survivor threshold on exp(z - max)
static constexpr int UROWB = 528;             // u-tile smem row stride (132 floats)

// load one stage (2 tiles x 128 rows x 128B), 8 cp.async per thread (256 thr)
__device__ __forceinline__ void load_stage(
    const __half* gA, const __half* gB,
    size_t Ks, int k0, uint32_t sbase, int tid)
{
    const __half* G[2] = {gA, gB};
#pragma unroll
    for (int j = 0; j < 8; j++) {
        const int idx = tid + j * 256;        // 0..2047
        const int tile = idx >> 10;
        const int c = idx & 1023;
        const int row = c >> 3, q = c & 7;
        cpasync16(sbase + tile * TILE_B + row * ROWB + q * 16,
                  G[tile] + (size_t)row * Ks + k0 + q * 8);
    }
}

// compute one k64 stage: 4 k16-steps x (4 m-frags x 4 n-frags)
__device__ __forceinline__ void compute_stage(
    uint32_t sbase, int wm, int wn, uint32_t aoff, uint32_t boff,
    float acc[4][4][4])
{
    const uint32_t sA = sbase;
    const uint32_t sB = sbase + TILE_B;
#pragma unroll
    for (int ks = 0; ks < 4; ks++) {
        const uint32_t kb = ks * 32;
        uint32_t bf[8];
#pragma unroll
        for (int f = 0; f < 2; f++) {
            uint32_t off = (wn * 32 + f * 16) * ROWB + kb + boff;
            ldsm4(bf + f * 4, sB + off);
        }
#pragma unroll
        for (int mf = 0; mf < 4; mf++) {
            uint32_t off = (wm * 64 + mf * 16) * ROWB + kb + aoff;
            uint32_t af[4];
            ldsm4(af, sA + off);
#pragma unroll
            for (int nf = 0; nf < 4; nf++)
                mma16816(acc[mf][nf], af, bf + nf * 2);
        }
    }
}

// ---------------------------------------------------------------------------
// quant_x: x -> fp16 + 0.5*row-sum (fp32) + init per-row max cell
// ---------------------------------------------------------------------------
__global__ __launch_bounds__(256) void quant_x(const float* __restrict__ x) {
    const int w = blockIdx.x * 8 + (threadIdx.x >> 5);
    const int lane = threadIdx.x & 31;
    const float4* row = (const float4*)(x + (size_t)w * Ddim);
    float s = 0.f;
#pragma unroll
    for (int i = 0; i < 8; i++) {
        float4 v = row[lane + 32 * i];
        s += (v.x + v.y) + (v.z + v.w);
        __half2 h01 = __floats2half2_rn(v.x, v.y);
        __half2 h23 = __floats2half2_rn(v.z, v.w);
        __half2* o = (__half2*)(g_x + (size_t)w * Ddim + (lane + 32 * i) * 4);
        o[0] = h01; o[1] = h23;
    }
#pragma unroll
    for (int o = 16; o > 0; o >>= 1) s += __shfl_xor_sync(0xFFFFFFFFu, s, o);
    if (lane == 0) {
        g_rs[w] = 0.5f * s;
        g_maxi[w] = 0x00800000u;   // encode(-FLT_MAX)
    }
}
// quant_p: (proto - 0.5) -> fp16 row-major
__global__ __launch_bounds__(256) void quant_p(const float* __restrict__ proto) {
    int idx = blockIdx.x * 256 + threadIdx.x;
    g_p[idx] = __float2half_rn(proto[idx] - 0.5f);
}

// ---------------------------------------------------------------------------
// K1: Z^T[b][n][p] = x.(proto-0.5)^T + 0.5*rowsum(x) + gumbel, plus per-(b,n)
// running max via ordered-uint atomicMax. u tile prefetched via cp.async into
// the dead pipeline buffers (1,2) during the last two GEMM stages.
// ---------------------------------------------------------------------------
__global__ __launch_bounds__(256, 2) void k1_logits(const float* __restrict__ u) {
    extern __shared__ char smem[];
    const uint32_t smem_b = smem_u32_of(smem);
    const int tid = threadIdx.x, lane = tid & 31, wid = tid >> 5;
    const int wm = wid & 1, wn = wid >> 1;
    const int bn = blockIdx.x, bp = blockIdx.y, b = blockIdx.z;

    const __half* gA = g_x + ((size_t)b * Ndim + bn * 128) * Ddim;
    const __half* gB = g_p + (size_t)(bp * 128) * Ddim;
    const float* ug = u + ((size_t)b * Pdim + (size_t)bp * 128) * Ndim + bn * 128;

    const uint32_t aoff = (uint32_t)((lane & 15) * ROWB + ((lane & 16) ? 16 : 0));
    const uint32_t boff = (uint32_t)(((lane & 7) + ((lane & 16) ? 8 : 0)) * ROWB
                                     + ((lane & 8) ? 16 : 0));
    float acc[4][4][4];
#pragma unroll
    for (int mf = 0; mf < 4; mf++)
#pragma unroll
        for (int nf = 0; nf < 4; nf++)
#pragma unroll
            for (int e = 0; e < 4; e++) acc[mf][nf][e] = 0.f;

    load_stage(gA, gB, (size_t)Ddim, 0, smem_b, tid);
    CP_COMMIT();
    load_stage(gA, gB, (size_t)Ddim, KT, smem_b + STAGE_B, tid);
    CP_COMMIT();

    const int T = Ddim / KT;   // 16
    int s_cur = 0, s_nxt = 2;
    for (int t = 0; t < T; t++) {
        CP_WAIT(1);
        __syncthreads();
        if (t + 2 < T) {
            load_stage(gA, gB, (size_t)Ddim, (t + 2) * KT,
                       smem_b + s_nxt * STAGE_B, tid);
            CP_COMMIT();
        } else {
            const int rbase = (t + 2 == T) ? 0 : 64;
#pragma unroll
            for (int j = 0; j < 8; j++) {
                int idx = tid + j * 256;
                int row = rbase + (idx >> 5), c4 = idx & 31;
                cpasync16(smem_b + STAGE_B + row * UROWB + c4 * 16,
                          ug + (size_t)row * Ndim + c4 * 4);
            }
            CP_COMMIT();
        }
        compute_stage(smem_b + s_cur * STAGE_B, wm, wn, aoff, boff, acc);
        s_cur = (s_cur == 2) ? 0 : s_cur + 1;
        s_nxt = (s_nxt == 2) ? 0 : s_nxt + 1;
    }

    CP_WAIT(0);
    __syncthreads();
    const float* u_s = (const float*)(smem + STAGE_B);

    const int gID = lane >> 2, tg = lane & 3;
#pragma unroll
    for (int mf = 0; mf < 4; mf++) {
#pragma unroll
        for (int r2 = 0; r2 < 2; r2++) {
            const int nl = wm * 64 + mf * 16 + gID + r2 * 8;
            const size_t rn = (size_t)b * Ndim + bn * 128 + nl;
            const float rsv = g_rs[rn];
            const size_t rowbase = rn * Pdim + bp * 128;
            float zmax = -3.4e38f;
#pragma unroll
            for (int nf = 0; nf < 4; nf++) {
                const int pl = wn * 32 + nf * 8 + tg * 2;
                float u0 = u_s[pl * 132 + nl];
                float u1 = u_s[(pl + 1) * 132 + nl];
                float2 z;
                z.x = acc[mf][nf][r2 * 2 + 0] + rsv - __logf(-__logf(u0));
                z.y = acc[mf][nf][r2 * 2 + 1] + rsv - __logf(-__logf(u1));
                *(float2*)&g_ZT[rowbase + pl] = z;
                zmax = fmaxf(zmax, fmaxf(z.x, z.y));
            }
            zmax = fmaxf(zmax, __shfl_xor_sync(0xFFFFFFFFu, zmax, 1));
            zmax = fmaxf(zmax, __shfl_xor_sync(0xFFFFFFFFu, zmax, 2));
            if (tg == 0) atomicMax(&g_maxi[rn], enc_f(zmax));
        }
    }
}

// ---------------------------------------------------------------------------
// K23 fused: warp-per-(b,n). Single pass over Z: exp, full sum, ballot the
// survivors (w > THR) and immediately accumulate w * protoC[p][:] into
// registers (survivor order identical to the old list order -> bit-identical
// output). Normalize by the full sum + 0.5 in the epilogue.
// ---------------------------------------------------------------------------
__global__ __launch_bounds__(256) void k23_fused(float* __restrict__ out) {
    int wid = threadIdx.x >> 5, lane = threadIdx.x & 31;
    int n = blockIdx.x * 8 + wid, b = blockIdx.y;
    size_t rn = (size_t)b * Ndim + n;
    const float4* __restrict__ row = (const float4*)(g_ZT + rn * Pdim);
    const float m = dec_f(g_maxi[rn]);   // exact max (ordered-uint bijection)

    float acc[32];
#pragma unroll
    for (int k = 0; k < 32; k++) acc[k] = 0.f;
    float s = 0.f;

#pragma unroll 2
    for (int i = 0; i < 16; i++) {
        int i4 = lane + 32 * i;
        float4 v = row[i4];
        float w4[4];
        w4[0] = __expf(v.x - m); w4[1] = __expf(v.y - m);
        w4[2] = __expf(v.z - m); w4[3] = __expf(v.w - m);
        s += (w4[0] + w4[1]) + (w4[2] + w4[3]);
#pragma unroll
        for (int j = 0; j < 4; j++) {
            unsigned msk = __ballot_sync(0xFFFFFFFFu, w4[j] > THR);
            while (msk) {
                int src = __ffs(msk) - 1;
                msk &= msk - 1;
                float w = __shfl_sync(0xFFFFFFFFu, w4[j], src);
                int p = (src + 32 * i) * 4 + j;
                const uint4* __restrict__ prow =
                    (const uint4*)(g_p + (size_t)p * Ddim);
                uint4 pk[4];
#pragma unroll
                for (int q = 0; q < 4; q++) pk[q] = prow[lane + 32 * q];
#pragma unroll
                for (int q = 0; q < 4; q++) {
                    const __half2* h = (const __half2*)&pk[q];
#pragma unroll
                    for (int t = 0; t < 4; t++) {
                        float2 f = __half22float2(h[t]);
                        acc[q * 8 + t * 2 + 0] = fmaf(w, f.x, acc[q * 8 + t * 2 + 0]);
                        acc[q * 8 + t * 2 + 1] = fmaf(w, f.y, acc[q * 8 + t * 2 + 1]);
                    }
                }
            }
        }
    }
#pragma unroll
    for (int o = 16; o > 0; o >>= 1) s += __shfl_xor_sync(0xFFFFFFFFu, s, o);
    const float inv = 1.0f / s;

    float* orow = out + rn * Ddim;
#pragma unroll
    for (int q = 0; q < 4; q++) {
        int d0 = (lane + 32 * q) * 8;
        float4 o0, o1;
        o0.x = acc[q * 8 + 0] * inv + 0.5f; o0.y = acc[q * 8 + 1] * inv + 0.5f;
        o0.z = acc[q * 8 + 2] * inv + 0.5f; o0.w = acc[q * 8 + 3] * inv + 0.5f;
        o1.x = acc[q * 8 + 4] * inv + 0.5f; o1.y = acc[q * 8 + 5] * inv + 0.5f;
        o1.z = acc[q * 8 + 6] * inv + 0.5f; o1.w = acc[q * 8 + 7] * inv + 0.5f;
        *(float4*)(orow + d0) = o0;
        *(float4*)(orow + d0 + 4) = o1;
    }
}

// ---------------------------------------------------------------------------
extern "C" void kernel_launch(void* const* d_in, const int* in_sizes, int n_in,
                              void* d_out, int out_size)
{
    (void)in_sizes; (void)n_in; (void)out_size;
    const float* x     = (const float*)d_in[0];  // [B, N, D]
    const float* u     = (const float*)d_in[1];  // [B, P, N]
    const float* proto = (const float*)d_in[2];  // [P, D]
    float* out = (float*)d_out;                  // [B, N, D]

    cudaFuncSetAttribute(k1_logits, cudaFuncAttributeMaxDynamicSharedMemorySize, DYN_SMEM);

    quant_x<<<(Bdim * Ndim) / 8, 256>>>(x);
    quant_p<<<(Pdim * Ddim) / 256, 256>>>(proto);

    dim3 g1(Ndim / 128, Pdim / 128, Bdim);
    k1_logits<<<g1, 256, DYN_SMEM>>>(u);

    dim3 g2(Ndim / 8, Bdim);
    k23_fused<<<g2, 256>>>(out);
}